// round 12
// baseline (speedup 1.0000x reference)
#include <cuda_runtime.h>
#include <cuda_bf16.h>
#include <cstdint>

// ---------------------------------------------------------------------------
// Problem constants
// ---------------------------------------------------------------------------
#define VOCAB 50257
#define DIM   768
#define VPAD  50304            // ceil(VOCAB/128)*128 = 393*128
#define NTILE 6                // 768 / 128
#define NPAIRS_T 21            // upper-triangle 128x128 tiles (mi<=ni)
#define KSPLIT 14              // split-K -> 21*14 = 294 CTAs (2 per SM)
#define EPS_F 1.1920929e-7f    // jnp.finfo(float32).eps

#define KC 64                  // K (vocab) elements per pipeline stage
#define KCHUNKS (VPAD / KC)    // 786
#define STAGE_BYTES 32768      // A tile 16KB + B tile 16KB (64 rows x 256B each)
#define NSTAGES 3
#define SMEM_K3 (NSTAGES * STAGE_BYTES)   // 96KB -> 2 CTAs/SM

#define REDUCE_GRID 256

// ---------------------------------------------------------------------------
// Device scratch (allocation-free: __device__ globals)
// ---------------------------------------------------------------------------
__device__ __align__(16) __nv_bfloat16 g_Wn[(size_t)VPAD * DIM];  // Wn, bf16, v-major
__device__ float  g_Diag[VOCAB];
__device__ float  g_G[DIM * DIM];                    // Gram accumulator (upper triangle)
__device__ double g_acc[2];                          // [0]=total_sq, [1]=diag_sq
__device__ unsigned g_done;                          // last-block flag for fused finalize

// ---------------------------------------------------------------------------
// PTX helpers (family-portable: cp.async / ldmatrix / mma.sync only)
// ---------------------------------------------------------------------------
__device__ __forceinline__ uint32_t smem_to_u32(const void* p) {
    uint32_t a;
    asm("{ .reg .u64 t; cvta.to.shared.u64 t, %1; cvt.u32.u64 %0, t; }" : "=r"(a) : "l"(p));
    return a;
}

__device__ __forceinline__ void cp_async16(uint32_t dst, const void* src) {
    asm volatile("cp.async.cg.shared.global [%0], [%1], 16;" :: "r"(dst), "l"(src));
}

// transposed ldmatrix: smem tile is [k][m] / [k][n]; fragments come out as
// the mma.row.col A/B layouts.
#define LDSM_X4T(r, addr) \
    asm volatile("ldmatrix.sync.aligned.m8n8.x4.trans.shared.b16 {%0,%1,%2,%3}, [%4];" \
        : "=r"((r)[0]), "=r"((r)[1]), "=r"((r)[2]), "=r"((r)[3]) : "r"(addr))

__device__ __forceinline__ void mma16816(float* c, const uint32_t* a, uint32_t b0, uint32_t b1) {
    asm volatile(
        "mma.sync.aligned.m16n8k16.row.col.f32.bf16.bf16.f32 "
        "{%0,%1,%2,%3}, {%4,%5,%6,%7}, {%8,%9}, {%0,%1,%2,%3};"
        : "+f"(c[0]), "+f"(c[1]), "+f"(c[2]), "+f"(c[3])
        : "r"(a[0]), "r"(a[1]), "r"(a[2]), "r"(a[3]), "r"(b0), "r"(b1));
}

// ---------------------------------------------------------------------------
// Kernel 1 (streaming prep): row stats + scale + bf16 quantize, row-major out.
// One warp per vocab row; fully-coalesced fp32 reads and 8B bf16 stores.
// Also zeroes g_G / g_acc / g_done.
// ---------------------------------------------------------------------------
__global__ void __launch_bounds__(256) prep_kernel(const float* __restrict__ W) {
    int tid = threadIdx.x;
    int wid = tid >> 5;
    int lane = tid & 31;

    // merged zero of scratch
    {
        int zi = blockIdx.x * 256 + tid;
        if (zi < DIM * DIM) g_G[zi] = 0.0f;
        if (blockIdx.x == 0 && tid < 2) g_acc[tid] = 0.0;
        if (blockIdx.x == 0 && tid == 2) g_done = 0u;
    }

    int v = blockIdx.x * 8 + wid;          // grid = VPAD/8
    float4 x[6];
    if (v < VOCAB) {
        const float4* rp = (const float4*)(W + (size_t)v * DIM);
        #pragma unroll
        for (int j = 0; j < 6; j++) x[j] = rp[lane + j * 32];
    } else {
        #pragma unroll
        for (int j = 0; j < 6; j++) x[j] = make_float4(0.f, 0.f, 0.f, 0.f);
    }
    float ssum = 0.0f;
    #pragma unroll
    for (int j = 0; j < 6; j++)
        ssum += x[j].x * x[j].x + x[j].y * x[j].y + x[j].z * x[j].z + x[j].w * x[j].w;
    #pragma unroll
    for (int off = 16; off; off >>= 1) ssum += __shfl_xor_sync(0xffffffffu, ssum, off);

    float m = ssum * (1.0f / DIM) + EPS_F;
    float sc = rsqrtf(m);
    if (lane == 0 && v < VOCAB) g_Diag[v] = ssum / m;   // = ||wn_v||^2

    uint2* orow = (uint2*)(g_Wn + (size_t)v * DIM);
    #pragma unroll
    for (int j = 0; j < 6; j++) {
        __nv_bfloat162 lo = __float22bfloat162_rn(make_float2(x[j].x * sc, x[j].y * sc));
        __nv_bfloat162 hi = __float22bfloat162_rn(make_float2(x[j].z * sc, x[j].w * sc));
        uint2 pk;
        pk.x = *(const uint32_t*)&lo;
        pk.y = *(const uint32_t*)&hi;
        orow[lane + j * 32] = pk;
    }
}

// ---------------------------------------------------------------------------
// Kernel 2: bf16 Gram GEMM via mma.sync (m16n8k16) + ldmatrix.trans.
// 4 warps/CTA, 64x64 warp tiles (2m x 2n) -> A/B smem-read redundancy 2x each
// (was 4x/2x), cutting LDSM port traffic from 96KB to 64KB per 64-k chunk.
// Fragments double-buffered across k-steps. 3-stage cp.async pipeline,
// 96KB smem, __launch_bounds__(128,2) -> 2 CTAs/SM (8 warps).
// Diagonal tiles skip the fully-lower 64x64 warp quadrant (reduce uses
// element-wise triangle weights, so lower-triangle entries are never read).
// ---------------------------------------------------------------------------
__global__ void __launch_bounds__(128, 2) gram_kernel() {
    extern __shared__ char smem[];
    uint32_t sbase = smem_to_u32(smem);
    int tid = threadIdx.x;
    int wid = tid >> 5;
    int lane = tid & 31;

    // decode (mi, ni) with mi <= ni, and K split range
    int t = blockIdx.x % NPAIRS_T;
    int split = blockIdx.x / NPAIRS_T;
    int mi = 0;
    while (t >= NTILE - mi) { t -= NTILE - mi; mi++; }
    int ni = mi + t;
    int c0 = (split * KCHUNKS) / KSPLIT;
    int c1 = ((split + 1) * KCHUNKS) / KSPLIT;
    int nk = c1 - c0;

    const int moff = mi * 128;
    const int noff = ni * 128;

    int warp_m = wid >> 1;          // 0..1
    int warp_n = wid & 1;           // 0..1
    int mbase = warp_m * 64;
    int nbase = warp_n * 64;
    // diagonal tile: warp (1,0) covers m in [64,128), n in [0,64) -> strictly
    // below the diagonal -> not needed (element-wise weights ignore i>j).
    bool active = !(mi == ni && warp_m == 1 && warp_n == 0);
    int sub = lane >> 3;
    int r8  = lane & 7;

    float acc[4][8][4];
    #pragma unroll
    for (int a = 0; a < 4; a++)
        #pragma unroll
        for (int b = 0; b < 8; b++)
            #pragma unroll
            for (int c = 0; c < 4; c++) acc[a][b][c] = 0.0f;

    // per-warp LDSM offsets within a stage tile (k-major, 256B rows, swizzled)
    // A matrices: sub -> (m-octet = sub&1, k-octet = sub>>1)
    uint32_t a_off[4];
    #pragma unroll
    for (int mt = 0; mt < 4; mt++) {
        int mcol = mbase + mt * 16 + (sub & 1) * 8;
        int ch = mcol >> 3;
        a_off[mt] = (uint32_t)(((sub >> 1) * 8 + r8) * 256) + (uint32_t)((ch ^ r8) * 16);
    }
    // B matrices: sub -> (k-octet = sub&1, n-octet = sub>>1)
    uint32_t b_off[4];
    #pragma unroll
    for (int np = 0; np < 4; np++) {
        int ncol = nbase + np * 16 + (sub >> 1) * 8;
        int ch = ncol >> 3;
        b_off[np] = (uint32_t)(((sub & 1) * 8 + r8) * 256) + (uint32_t)((ch ^ r8) * 16);
    }

    // prologue: fill 2 stages (prefetch distance 2). 128 threads: each thread
    // copies 8 A chunks + 8 B chunks (16B each) per stage.
    #pragma unroll 1
    for (int s = 0; s < 2; s++) {
        if (s < nk) {
            uint32_t stA = sbase + s * STAGE_BYTES;
            uint32_t stB = stA + 16384;
            size_t kbase = (size_t)(c0 + s) * KC;
            #pragma unroll
            for (int i = 0; i < 8; i++) {
                int idx = i * 128 + tid;
                int row = idx >> 4;
                int ch  = idx & 15;
                uint32_t d = (uint32_t)row * 256 + (uint32_t)((ch ^ (row & 7)) * 16);
                const __nv_bfloat16* src = g_Wn + (kbase + row) * DIM + ch * 8;
                cp_async16(stA + d, src + moff);
                cp_async16(stB + d, src + noff);
            }
        }
        asm volatile("cp.async.commit_group;");
    }

    int buf = 0;
    #pragma unroll 1
    for (int it = 0; it < nk; it++) {
        asm volatile("cp.async.wait_group 1;");
        __syncthreads();

        uint32_t stA = sbase + buf * STAGE_BYTES;
        uint32_t stB = stA + 16384;

        if (active) {
            uint32_t a[2][4][4], b[2][4][4];
            #pragma unroll
            for (int mt = 0; mt < 4; mt++) LDSM_X4T(a[0][mt], stA + a_off[mt]);
            #pragma unroll
            for (int np = 0; np < 4; np++) LDSM_X4T(b[0][np], stB + b_off[np]);
            #pragma unroll
            for (int ks = 0; ks < 4; ks++) {
                int cb = ks & 1, nb = cb ^ 1;
                if (ks < 3) {
                    uint32_t kofs = (uint32_t)(ks + 1) * 4096;   // 16 k-rows * 256B
                    #pragma unroll
                    for (int mt = 0; mt < 4; mt++) LDSM_X4T(a[nb][mt], stA + a_off[mt] + kofs);
                    #pragma unroll
                    for (int np = 0; np < 4; np++) LDSM_X4T(b[nb][np], stB + b_off[np] + kofs);
                }
                #pragma unroll
                for (int mt = 0; mt < 4; mt++)
                    #pragma unroll
                    for (int nt = 0; nt < 8; nt++)
                        mma16816(acc[mt][nt], a[cb][mt],
                                 b[cb][nt >> 1][(nt & 1) * 2],
                                 b[cb][nt >> 1][(nt & 1) * 2 + 1]);
            }
        }

        // prefetch stage it+2 into buffer (buf+2)%3 (freed last iter)
        if (it + 2 < nk) {
            int s = it + 2;
            int pb = buf + 2; if (pb >= 3) pb -= 3;
            uint32_t pA = sbase + pb * STAGE_BYTES;
            uint32_t pB = pA + 16384;
            size_t kbase = (size_t)(c0 + s) * KC;
            #pragma unroll
            for (int i = 0; i < 8; i++) {
                int idx = i * 128 + tid;
                int row = idx >> 4;
                int ch  = idx & 15;
                uint32_t d = (uint32_t)row * 256 + (uint32_t)((ch ^ (row & 7)) * 16);
                const __nv_bfloat16* src = g_Wn + (kbase + row) * DIM + ch * 8;
                cp_async16(pA + d, src + moff);
                cp_async16(pB + d, src + noff);
            }
        }
        asm volatile("cp.async.commit_group;");
        if (++buf == 3) buf = 0;
    }

    // epilogue: merge split-K partials into g_G
    if (active) {
        int g = lane >> 2;
        int tt = lane & 3;
        #pragma unroll
        for (int mt = 0; mt < 4; mt++) {
            int m = mi * 128 + mbase + mt * 16 + g;
            #pragma unroll
            for (int nt = 0; nt < 8; nt++) {
                int n = ni * 128 + nbase + nt * 8 + tt * 2;
                float* p0 = g_G + (size_t)m * DIM + n;
                float* p1 = g_G + (size_t)(m + 8) * DIM + n;
                atomicAdd(p0 + 0, acc[mt][nt][0]);
                atomicAdd(p0 + 1, acc[mt][nt][1]);
                atomicAdd(p1 + 0, acc[mt][nt][2]);
                atomicAdd(p1 + 1, acc[mt][nt][3]);
            }
        }
    }
}

// ---------------------------------------------------------------------------
// Kernel 3 (fused reduce+finalize): element-wise triangle weights —
// total_sq = 2*sum_{i<j} G_ij^2 + sum_i G_ii^2 (lower entries never read),
// diag_sq = sum over vocab of ||wn_v||^4. Last block finalizes the scalar.
// ---------------------------------------------------------------------------
__global__ void reduce_kernel(float* __restrict__ out) {
    const int n1 = DIM * DIM;
    const int tot = n1 + VOCAB;
    double accT = 0.0, accD = 0.0;
    for (int idx = blockIdx.x * 256 + threadIdx.x; idx < tot; idx += REDUCE_GRID * 256) {
        if (idx < n1) {
            int i = idx / DIM;
            int j = idx - i * DIM;
            double g = (double)g_G[idx];
            double w = (i < j) ? 2.0 : (i == j ? 1.0 : 0.0);
            accT += w * g * g;
        } else {
            double d = (double)g_Diag[idx - n1];
            accD += d * d;
        }
    }
    #pragma unroll
    for (int off = 16; off; off >>= 1) {
        accT += __shfl_xor_sync(0xffffffffu, accT, off);
        accD += __shfl_xor_sync(0xffffffffu, accD, off);
    }
    __shared__ double sT[8], sD[8];
    __shared__ bool is_last;
    if ((threadIdx.x & 31) == 0) { sT[threadIdx.x >> 5] = accT; sD[threadIdx.x >> 5] = accD; }
    __syncthreads();
    if (threadIdx.x == 0) {
        double tT = 0.0, tD = 0.0;
        #pragma unroll
        for (int i = 0; i < 8; i++) { tT += sT[i]; tD += sD[i]; }
        atomicAdd(&g_acc[0], tT);
        atomicAdd(&g_acc[1], tD);
        __threadfence();
        unsigned prev = atomicAdd(&g_done, 1u);
        is_last = (prev == REDUCE_GRID - 1);
    }
    __syncthreads();
    if (is_last && threadIdx.x == 0) {
        double n_pairs = (double)VOCAB * (double)(VOCAB - 1) * 0.5;
        out[0] = (float)((g_acc[0] - g_acc[1]) * 0.5 / n_pairs);
    }
}

// ---------------------------------------------------------------------------
// Launch
// ---------------------------------------------------------------------------
extern "C" void kernel_launch(void* const* d_in, const int* in_sizes, int n_in,
                              void* d_out, int out_size) {
    (void)in_sizes; (void)n_in; (void)out_size;
    const float* W = (const float*)d_in[0];
    float* out = (float*)d_out;

    cudaFuncSetAttribute(gram_kernel, cudaFuncAttributeMaxDynamicSharedMemorySize, SMEM_K3);

    prep_kernel<<<VPAD / 8, 256>>>(W);
    gram_kernel<<<NPAIRS_T * KSPLIT, 128, SMEM_K3>>>();
    reduce_kernel<<<REDUCE_GRID, 256>>>(out);
}